// round 9
// baseline (speedup 1.0000x reference)
#include <cuda_runtime.h>
#include <cuda_fp16.h>
#include <cstdint>

// ─────────────────────────────────────────────────────────────────────────────
// KPConv fused: one CTA owns 128 query points end-to-end. Producer phase
// (gather + kernel points + phase-4 reduction, fp32 FFMA2) writes the 128x640
// fp16 weighted tile straight into shared memory (XOR-swizzled); GEMM phase
// (fp16 HMMA, fp32 accum) multiplies it against W streamed via a 3-stage
// cp.async ring that was prefetching during the producer phase.
// tcgen05 unavailable (harness PTX target is sm_103, not sm_103a).
// ─────────────────────────────────────────────────────────────────────────────

namespace {

typedef unsigned long long u64;

constexpr int H    = 26;
constexpr int KP   = 10;
constexpr int CIN  = 64;
constexpr int COUT = 128;
constexpr int KDIM = KP * CIN;   // 640
constexpr int NT   = 256;        // 8 warps
constexpr float INV_EXT = 1.0f / 1.2f;
constexpr int MAXN = 65536;

// Scratch (device-global; allocation in kernel_launch is forbidden).
__device__ __half g_B[(size_t)COUT * KDIM];   // [o][k*64+i]
__device__ __half g_X[(size_t)MAXN * CIN];    // fp16 copy of x

// A tile geometry in smem: 128 rows x 1280 B (640 fp16), XOR swizzle:
//   byte(row, colB) = row*1280 + (colB ^ ((row & 7) << 4))
constexpr int APITCH = 1280;
constexpr int ASZ    = 128 * APITCH;          // 163840

// B ring: chunks of 128 rows x 32 fp16, pitch 80 B (conflict-free ldmatrix).
constexpr int KT      = 32;
constexpr int BPITCH  = 80;
constexpr int BTSZ    = 128 * BPITCH;         // 10240
constexpr int NBST    = 3;
constexpr int NKT     = KDIM / KT;            // 20

struct FSmem {
  char  A[ASZ];
  char  Bring[NBST][BTSZ];
  u64   genWT2[42 * 32];        // [m2][j] packed gen_W pairs (j<30 used)
  float genB[32];
  float sP[8][4][84];           // padded neighbor vectors (per warp, 4 pts)
  float sKP[8][4][32];          // kernel points
  alignas(8) float swv[8][H * 10];  // [h][k] influence weights (1 pt at a time)
  int   sIdx[8][4][H];          // neighbor indices
};
constexpr int FSMEM = sizeof(FSmem);   // ~231 KB

__device__ __forceinline__ uint32_t smem_u32(const void* p) {
  uint32_t a;
  asm("{ .reg .u64 t; cvta.to.shared.u64 t, %1; cvt.u32.u64 %0, t; }"
      : "=r"(a) : "l"(p));
  return a;
}

__device__ __forceinline__ u64 ffma2(u64 a, u64 b, u64 c) {
  u64 d;
  asm("fma.rn.f32x2 %0, %1, %2, %3;" : "=l"(d) : "l"(a), "l"(b), "l"(c));
  return d;
}
__device__ __forceinline__ u64 pack2(float lo, float hi) {
  u64 d;
  asm("mov.b64 %0, {%1, %2};" : "=l"(d) : "f"(lo), "f"(hi));
  return d;
}
__device__ __forceinline__ float2 unpack2(u64 v) {
  float2 r;
  asm("mov.b64 {%0, %1}, %2;" : "=f"(r.x), "=f"(r.y) : "l"(v));
  return r;
}

__device__ __forceinline__ void cp16(uint32_t dst, const void* src) {
  asm volatile("cp.async.cg.shared.global [%0], [%1], 16;"
               :: "r"(dst), "l"(src) : "memory");
}
__device__ __forceinline__ void cp_commit() {
  asm volatile("cp.async.commit_group;" ::: "memory");
}
__device__ __forceinline__ void cp_wait1() {
  asm volatile("cp.async.wait_group 1;" ::: "memory");
}

__device__ __forceinline__ void ldm4(uint32_t* r, uint32_t addr) {
  asm volatile("ldmatrix.sync.aligned.m8n8.x4.shared.b16 {%0,%1,%2,%3}, [%4];"
               : "=r"(r[0]), "=r"(r[1]), "=r"(r[2]), "=r"(r[3]) : "r"(addr));
}

__device__ __forceinline__ void mma16816(float* d, const uint32_t* a,
                                         const uint32_t* b) {
  asm volatile(
      "mma.sync.aligned.m16n8k16.row.col.f32.f16.f16.f32 "
      "{%0,%1,%2,%3}, {%4,%5,%6,%7}, {%8,%9}, {%0,%1,%2,%3};"
      : "+f"(d[0]), "+f"(d[1]), "+f"(d[2]), "+f"(d[3])
      : "r"(a[0]), "r"(a[1]), "r"(a[2]), "r"(a[3]), "r"(b[0]), "r"(b[1]));
}

// ───────────────────── Kernel 0: prep (x→fp16, W→fp16 transposed) ───────────────

__global__ void prep_kernel(const float* __restrict__ x,
                            const float* __restrict__ weights,
                            int total_x)
{
  const int gid    = blockIdx.x * blockDim.x + threadIdx.x;
  const int stride = gridDim.x * blockDim.x;

  const int nv = total_x / 4;
  const float4* xv = reinterpret_cast<const float4*>(x);
  for (int i = gid; i < nv; i += stride) {
    const float4 v = xv[i];
    __half2* dst = reinterpret_cast<__half2*>(g_X + (size_t)i * 4);
    dst[0] = __floats2half2_rn(v.x, v.y);
    dst[1] = __floats2half2_rn(v.z, v.w);
  }
  for (int t = gid; t < KDIM * COUT; t += stride) {
    const int o  = t / KDIM;
    const int ki = t - o * KDIM;
    g_B[t] = __float2half_rn(weights[(size_t)ki * COUT + o]);
  }
}

// ───────────────────── Fused kernel: produce A tile + GEMM ─────────────────────

__global__ void fused_kernel(const float* __restrict__ q_pts,
                             const float* __restrict__ s_pts,
                             const float* __restrict__ genW,
                             const float* __restrict__ genB,
                             const int*   __restrict__ inds,
                             float*       __restrict__ out,
                             int N, int Ns)
{
  extern __shared__ char smraw[];
  FSmem& sm = *reinterpret_cast<FSmem*>(smraw);
  const uint32_t sbA = smem_u32(sm.A);
  const uint32_t sbB = smem_u32(sm.Bring);
  const int tid  = threadIdx.x;
  const int lane = tid & 31;
  const int wid  = tid >> 5;
  const size_t n0 = (size_t)blockIdx.x * 128;

  // B-ring chunk loader (128 rows x 32 fp16, pitch 80).
  auto load_bstage = [&](int st, int kc) {
    const uint32_t base = sbB + st * BTSZ;
    #pragma unroll
    for (int i = 0; i < 2; ++i) {
      const int id = tid + i * NT;
      const int r  = id >> 2;
      const int c  = id & 3;
      cp16(base + r * BPITCH + c * 16,
           g_B + (size_t)r * KDIM + kc * KT + c * 8);
    }
  };

  // Kick off B prefetch — overlaps the entire producer phase.
  load_bstage(0, 0); cp_commit();
  load_bstage(1, 1); cp_commit();

  // Stage gen_W as packed m-pairs (j-padded to 32 for conflict-free LDS).
  for (int t = tid; t < 42 * 32; t += NT) {
    const int j  = t & 31;
    const int m2 = t >> 5;
    sm.genWT2[t] = (j < 30)
        ? pack2(genW[j * 84 + 2 * m2], genW[j * 84 + 2 * m2 + 1]) : 0;
  }
  if (tid < 30) sm.genB[tid] = genB[tid];
  __syncthreads();

  // ════════════════ Producer phase: 16 points per warp, 4 batches of 4 ════════════════
  for (int bt = 0; bt < 4; ++bt) {
    const int nw = (int)n0 + wid * 16 + bt * 4;   // first point of this batch

    __syncwarp();   // prior batch's scratch reads complete

    // Phase 1 (batched 4 points): all index+coord gathers in flight at once.
    if (lane < H) {
      int jj[4];
      #pragma unroll
      for (int p = 0; p < 4; ++p) {
        const int n = nw + p;
        jj[p] = (n < N) ? inds[(size_t)n * H + lane] : 0;
      }
      float cx[4], cy[4], cz[4];
      #pragma unroll
      for (int p = 0; p < 4; ++p) {
        int j = jj[p];
        if (j >= 0 && j < Ns) {
          cx[p] = s_pts[3 * j + 0];
          cy[p] = s_pts[3 * j + 1];
          cz[p] = s_pts[3 * j + 2];
        } else {
          cx[p] = cy[p] = cz[p] = 1e6f;   // shadow point -> zero influence
          jj[p] = 0;
        }
      }
      #pragma unroll
      for (int p = 0; p < 4; ++p) {
        const int n = nw + p;
        if (n < N) {
          const float qx = q_pts[3 * n + 0];
          const float qy = q_pts[3 * n + 1];
          const float qz = q_pts[3 * n + 2];
          sm.sP[wid][p][lane * 3 + 0] = cx[p] - qx;
          sm.sP[wid][p][lane * 3 + 1] = cy[p] - qy;
          sm.sP[wid][p][lane * 3 + 2] = cz[p] - qz;
          sm.sIdx[wid][p][lane] = jj[p];
        }
      }
    } else if (lane < 28) {
      const int b = lane - H;
      #pragma unroll
      for (int p = 0; p < 4; ++p) {
        sm.sP[wid][p][78 + b * 3 + 0] = -1.0f;
        sm.sP[wid][p][78 + b * 3 + 1] = -1.0f;
        sm.sP[wid][p][78 + b * 3 + 2] = -1.0f;
      }
    }
    __syncwarp();

    // Phase 2 (batched): kp = gen_W @ p_vec + gen_b; 8 independent chains.
    if (lane < 30) {
      u64 aA[4] = {0, 0, 0, 0}, aB[4] = {0, 0, 0, 0};
      const u64* pp0 = reinterpret_cast<const u64*>(&sm.sP[wid][0][0]);
      const u64* pp1 = reinterpret_cast<const u64*>(&sm.sP[wid][1][0]);
      const u64* pp2 = reinterpret_cast<const u64*>(&sm.sP[wid][2][0]);
      const u64* pp3 = reinterpret_cast<const u64*>(&sm.sP[wid][3][0]);
      #pragma unroll 7
      for (int m2 = 0; m2 < 21; ++m2) {
        const u64 wA = sm.genWT2[m2 * 32 + lane];
        const u64 wB = sm.genWT2[(m2 + 21) * 32 + lane];
        aA[0] = ffma2(wA, pp0[m2], aA[0]);  aB[0] = ffma2(wB, pp0[m2 + 21], aB[0]);
        aA[1] = ffma2(wA, pp1[m2], aA[1]);  aB[1] = ffma2(wB, pp1[m2 + 21], aB[1]);
        aA[2] = ffma2(wA, pp2[m2], aA[2]);  aB[2] = ffma2(wB, pp2[m2 + 21], aB[2]);
        aA[3] = ffma2(wA, pp3[m2], aA[3]);  aB[3] = ffma2(wB, pp3[m2 + 21], aB[3]);
      }
      const float gb = sm.genB[lane];
      #pragma unroll
      for (int p = 0; p < 4; ++p) {
        const float2 ra = unpack2(aA[p]);
        const float2 rb = unpack2(aB[p]);
        sm.sKP[wid][p][lane] = (ra.x + ra.y) + (rb.x + rb.y) + gb;
      }
    }
    __syncwarp();

    // Phases 3-4 per point.
    for (int p = 0; p < 4; ++p) {
      const int n = nw + p;
      if (n >= N) continue;   // warp-uniform

      const int* idx = &sm.sIdx[wid][p][0];

      // Prefetch gather batch 0 (h=0..8) before phase 3 (hides LDG latency).
      __half2 xb[9];
      #pragma unroll
      for (int hh = 0; hh < 9; ++hh)
        xb[hh] = *reinterpret_cast<const __half2*>(
            g_X + (size_t)idx[hh] * CIN + 2 * lane);

      __syncwarp();   // prior point's swv reads done before overwrite

      // Phase 3: w[h][k] = relu(1 - ||nbr - kp|| / ext).
      for (int t = lane; t < KP * H; t += 32) {
        const int k = t / H;
        const int h = t - k * H;
        const float dx = sm.sP[wid][p][h * 3 + 0] - sm.sKP[wid][p][k * 3 + 0];
        const float dy = sm.sP[wid][p][h * 3 + 1] - sm.sKP[wid][p][k * 3 + 1];
        const float dz = sm.sP[wid][p][h * 3 + 2] - sm.sKP[wid][p][k * 3 + 2];
        const float d  = sqrtf(fmaf(dx, dx, fmaf(dy, dy, dz * dz)));
        sm.swv[wid][h * 10 + k] = fmaxf(1.0f - d * INV_EXT, 0.0f);
      }
      __syncwarp();

      u64 acc2[5][2];
      #pragma unroll
      for (int kk = 0; kk < 5; ++kk) { acc2[kk][0] = 0; acc2[kk][1] = 0; }

      auto accum = [&](int h, __half2 xh) {
        const float2 xv = __half22float2(xh);
        const u64 x0 = pack2(xv.x, xv.x);
        const u64 x1 = pack2(xv.y, xv.y);
        const u64* wp = reinterpret_cast<const u64*>(&sm.swv[wid][h * 10]);
        #pragma unroll
        for (int kk = 0; kk < 5; ++kk) {
          const u64 w2 = wp[kk];
          acc2[kk][0] = ffma2(w2, x0, acc2[kk][0]);
          acc2[kk][1] = ffma2(w2, x1, acc2[kk][1]);
        }
      };

      __half2 xc[9];
      #pragma unroll
      for (int hh = 0; hh < 9; ++hh)
        xc[hh] = *reinterpret_cast<const __half2*>(
            g_X + (size_t)idx[9 + hh] * CIN + 2 * lane);
      #pragma unroll
      for (int hh = 0; hh < 9; ++hh) accum(hh, xb[hh]);

      #pragma unroll
      for (int hh = 0; hh < 8; ++hh)
        xb[hh] = *reinterpret_cast<const __half2*>(
            g_X + (size_t)idx[18 + hh] * CIN + 2 * lane);
      #pragma unroll
      for (int hh = 0; hh < 9; ++hh) accum(9 + hh, xc[hh]);
      #pragma unroll
      for (int hh = 0; hh < 8; ++hh) accum(18 + hh, xb[hh]);

      // Store weighted row straight to smem A (XOR-swizzled, conflict-free).
      const int row = wid * 16 + bt * 4 + p;
      const uint32_t rbase = row * APITCH;
      const uint32_t rsw   = (row & 7) << 4;
      #pragma unroll
      for (int kk = 0; kk < 5; ++kk) {
        const float2 a0 = unpack2(acc2[kk][0]);   // col c0: (k even, k odd)
        const float2 a1 = unpack2(acc2[kk][1]);   // col c1
        const uint32_t c0 = ((2 * kk) * 128 + lane * 4) ^ rsw;
        const uint32_t c1 = ((2 * kk + 1) * 128 + lane * 4) ^ rsw;
        *reinterpret_cast<__half2*>(sm.A + rbase + c0) =
            __floats2half2_rn(a0.x, a1.x);
        *reinterpret_cast<__half2*>(sm.A + rbase + c1) =
            __floats2half2_rn(a0.y, a1.y);
      }
    }
  }

  __syncthreads();   // A tile complete; B stages 0-1 long since landed

  // ════════════════ GEMM phase: out[128,128] = A[128,640] @ B^T ════════════════
  // 8 warps in 4x2 grid of 32x64 tiles; A from smem, B via 3-stage ring.
  const int wr = wid >> 1;        // 0..3 -> rows wr*32
  const int wc = wid & 1;         // 0..1 -> cols wc*64

  const int arow  = lane & 15;
  const int acolB = (lane >> 4) * 16;
  const int brow  = (lane & 7) + ((lane >> 4) << 3);
  const int bcolB = ((lane >> 3) & 1) * 16;

  float acc[2][8][4];
  #pragma unroll
  for (int mi = 0; mi < 2; ++mi)
    #pragma unroll
    for (int ni = 0; ni < 8; ++ni)
      #pragma unroll
      for (int j = 0; j < 4; ++j) acc[mi][ni][j] = 0.f;

  for (int kc = 0; kc < NKT; ++kc) {
    const int st = kc % NBST;
    cp_wait1();        // stage kc resident (only kc+1 may be pending)
    __syncthreads();   // cp.async visibility + slot protection

    if (kc + 2 < NKT) load_bstage((kc + 2) % NBST, kc + 2);
    cp_commit();

    const uint32_t tB = sbB + st * BTSZ;

    #pragma unroll
    for (int ks = 0; ks < 2; ++ks) {
      uint32_t ah[2][4], bh[8][2];
      #pragma unroll
      for (int mi = 0; mi < 2; ++mi) {
        const int r = wr * 32 + mi * 16 + arow;
        const uint32_t ao =
            r * APITCH + ((kc * 64 + ks * 32 + acolB) ^ ((r & 7) << 4));
        ldm4(ah[mi], sbA + ao);
      }
      #pragma unroll
      for (int bi = 0; bi < 4; ++bi) {
        const uint32_t bo =
            (wc * 64 + bi * 16 + brow) * BPITCH + ks * 32 + bcolB;
        uint32_t t4[4];
        ldm4(t4, tB + bo);
        bh[2 * bi][0] = t4[0]; bh[2 * bi][1] = t4[1];
        bh[2 * bi + 1][0] = t4[2]; bh[2 * bi + 1][1] = t4[3];
      }
      #pragma unroll
      for (int mi = 0; mi < 2; ++mi)
        #pragma unroll
        for (int ni = 0; ni < 8; ++ni)
          mma16816(acc[mi][ni], ah[mi], bh[ni]);
    }
  }

  const int trow = lane >> 2;
  const int tcol = (lane & 3) * 2;
  #pragma unroll
  for (int mi = 0; mi < 2; ++mi) {
    const size_t row = n0 + wr * 32 + mi * 16 + trow;
    #pragma unroll
    for (int ni = 0; ni < 8; ++ni) {
      const int col = wc * 64 + ni * 8 + tcol;
      if (row < (size_t)N) {
        *reinterpret_cast<float2*>(out + row * COUT + col) =
            make_float2(acc[mi][ni][0], acc[mi][ni][1]);
        *reinterpret_cast<float2*>(out + (row + 8) * COUT + col) =
            make_float2(acc[mi][ni][2], acc[mi][ni][3]);
      }
    }
  }
}

}  // namespace

// ───────────────────────────── launch ─────────────────────────────

extern "C" void kernel_launch(void* const* d_in, const int* in_sizes, int n_in,
                              void* d_out, int out_size) {
  const float* q_pts = (const float*)d_in[0];
  const float* s_pts = (const float*)d_in[1];
  const float* x     = (const float*)d_in[2];
  const float* genW  = (const float*)d_in[3];
  const float* genB  = (const float*)d_in[4];
  const float* wts   = (const float*)d_in[5];
  const int*   inds  = (const int*)d_in[6];
  float* out = (float*)d_out;

  int N  = in_sizes[0] / 3;
  const int Ns = in_sizes[1] / 3;
  if (N > MAXN) N = MAXN;

  cudaFuncSetAttribute(fused_kernel,
                       cudaFuncAttributeMaxDynamicSharedMemorySize, FSMEM);

  prep_kernel<<<1024, 256>>>(x, wts, N * CIN);

  const int grid = (N + 127) / 128;
  fused_kernel<<<grid, NT, FSMEM>>>(q_pts, s_pts, genW, genB, inds, out, N, Ns);
}

// round 10
// speedup vs baseline: 1.3809x; 1.3809x over previous
#include <cuda_runtime.h>
#include <cuda_fp16.h>
#include <cstdint>

// ─────────────────────────────────────────────────────────────────────────────
// KPConv: prep (x→fp16, W transpose→fp16) ➜ producer where phase 4
// (weighted[10x64] = w[10x26] @ x_gather[26x64]) runs on tensor cores per
// point (cp.async gather into smem overlapped with phase-3 weight calc)
// ➜ fp16 HMMA GEMM (round-8 version, unchanged).
// tcgen05 unavailable (harness PTX target is sm_103, not sm_103a).
// ─────────────────────────────────────────────────────────────────────────────

namespace {

typedef unsigned long long u64;

constexpr int H    = 26;
constexpr int KP   = 10;
constexpr int CIN  = 64;
constexpr int COUT = 128;
constexpr int KDIM = KP * CIN;   // 640
constexpr int TILE = 32;         // points per producer CTA
constexpr int NT   = 256;        // 8 warps
constexpr float INV_EXT = 1.0f / 1.2f;
constexpr int MAXN = 65536;

__device__ __half g_A[(size_t)MAXN * KDIM];
__device__ __half g_B[(size_t)COUT * KDIM];   // [o][k*64+i]
__device__ __half g_X[(size_t)MAXN * CIN];    // fp16 copy of x

__device__ __forceinline__ uint32_t smem_u32(const void* p) {
  uint32_t a;
  asm("{ .reg .u64 t; cvta.to.shared.u64 t, %1; cvt.u32.u64 %0, t; }"
      : "=r"(a) : "l"(p));
  return a;
}

__device__ __forceinline__ u64 ffma2(u64 a, u64 b, u64 c) {
  u64 d;
  asm("fma.rn.f32x2 %0, %1, %2, %3;" : "=l"(d) : "l"(a), "l"(b), "l"(c));
  return d;
}
__device__ __forceinline__ u64 pack2(float lo, float hi) {
  u64 d;
  asm("mov.b64 %0, {%1, %2};" : "=l"(d) : "f"(lo), "f"(hi));
  return d;
}
__device__ __forceinline__ float2 unpack2(u64 v) {
  float2 r;
  asm("mov.b64 {%0, %1}, %2;" : "=f"(r.x), "=f"(r.y) : "l"(v));
  return r;
}

__device__ __forceinline__ void cp16(uint32_t dst, const void* src) {
  asm volatile("cp.async.cg.shared.global [%0], [%1], 16;"
               :: "r"(dst), "l"(src) : "memory");
}
__device__ __forceinline__ void cp_commit() {
  asm volatile("cp.async.commit_group;" ::: "memory");
}
__device__ __forceinline__ void cp_wait0() {
  asm volatile("cp.async.wait_group 0;" ::: "memory");
}
__device__ __forceinline__ void cp_wait2() {
  asm volatile("cp.async.wait_group 2;" ::: "memory");
}

__device__ __forceinline__ void ldm4(uint32_t* r, uint32_t addr) {
  asm volatile("ldmatrix.sync.aligned.m8n8.x4.shared.b16 {%0,%1,%2,%3}, [%4];"
               : "=r"(r[0]), "=r"(r[1]), "=r"(r[2]), "=r"(r[3]) : "r"(addr));
}
__device__ __forceinline__ void ldm4t(uint32_t* r, uint32_t addr) {
  asm volatile("ldmatrix.sync.aligned.m8n8.x4.trans.shared.b16 {%0,%1,%2,%3}, [%4];"
               : "=r"(r[0]), "=r"(r[1]), "=r"(r[2]), "=r"(r[3]) : "r"(addr));
}

__device__ __forceinline__ void mma16816(float* d, const uint32_t* a,
                                         const uint32_t* b) {
  asm volatile(
      "mma.sync.aligned.m16n8k16.row.col.f32.f16.f16.f32 "
      "{%0,%1,%2,%3}, {%4,%5,%6,%7}, {%8,%9}, {%0,%1,%2,%3};"
      : "+f"(d[0]), "+f"(d[1]), "+f"(d[2]), "+f"(d[3])
      : "r"(a[0]), "r"(a[1]), "r"(a[2]), "r"(a[3]), "r"(b[0]), "r"(b[1]));
}

// ───────────────────── Kernel 0: prep (x→fp16, W→fp16 transposed) ───────────────

__global__ void prep_kernel(const float* __restrict__ x,
                            const float* __restrict__ weights,
                            int total_x)
{
  const int gid    = blockIdx.x * blockDim.x + threadIdx.x;
  const int stride = gridDim.x * blockDim.x;

  const int nv = total_x / 4;
  const float4* xv = reinterpret_cast<const float4*>(x);
  for (int i = gid; i < nv; i += stride) {
    const float4 v = xv[i];
    __half2* dst = reinterpret_cast<__half2*>(g_X + (size_t)i * 4);
    dst[0] = __floats2half2_rn(v.x, v.y);
    dst[1] = __floats2half2_rn(v.z, v.w);
  }
  for (int t = gid; t < KDIM * COUT; t += stride) {
    const int o  = t / KDIM;
    const int ki = t - o * KDIM;
    g_B[t] = __float2half_rn(weights[(size_t)ki * COUT + o]);
  }
}

// ───────────────────── Kernel 1: producer (HMMA phase 4) ─────────────────────
// Per-warp smem:
//   xT: 32 rows x 64 fp16 (128 B), XOR swizzle (c16B ^ ((h&7)<<4)) — B operand
//   wT: 16 rows x 40 fp16 (80 B pitch) — A operand (k rows, h cols)

struct PSmem {
  char  xT[8][32 * 128];        // 32768 B
  __half wT[8][16 * 40];        // 10240 B
  u64   genWT2[42 * 32];        // 10752 B
  float genB[32];
  float sP[8][4][84];           // 10752 B
  float sKP[8][4][32];          // 4096 B
  int   sIdx[8][4][H];          // 3328 B
};
constexpr int PSMEM = sizeof(PSmem);   // ~71 KB

__global__ void __launch_bounds__(NT, 3)
producer_kernel(const float* __restrict__ q_pts,
                const float* __restrict__ s_pts,
                const float* __restrict__ genW,
                const float* __restrict__ genB,
                const int*   __restrict__ inds,
                int N, int Ns)
{
  extern __shared__ char smraw[];
  PSmem& sm = *reinterpret_cast<PSmem*>(smraw);
  const int tid  = threadIdx.x;
  const int lane = tid & 31;
  const int wid  = tid >> 5;

  // Stage gen_W packed pairs; zero xT (pad rows must be 0) and wT (pad region).
  for (int t = tid; t < 42 * 32; t += NT) {
    const int j  = t & 31;
    const int m2 = t >> 5;
    sm.genWT2[t] = (j < 30)
        ? pack2(genW[j * 84 + 2 * m2], genW[j * 84 + 2 * m2 + 1]) : 0;
  }
  if (tid < 30) sm.genB[tid] = genB[tid];
  {
    uint4 z = make_uint4(0, 0, 0, 0);
    uint4* xz = reinterpret_cast<uint4*>(sm.xT);
    for (int t = tid; t < (8 * 32 * 128) / 16; t += NT) xz[t] = z;
    uint4* wz = reinterpret_cast<uint4*>(sm.wT);
    for (int t = tid; t < (8 * 16 * 80) / 16; t += NT) wz[t] = z;
  }
  __syncthreads();

  const int nw = blockIdx.x * TILE + wid * 4;   // first point of this warp

  // ── Phase 1 (batched 4 points): all gathers in flight at once. ──
  if (lane < H) {
    int jj[4];
    #pragma unroll
    for (int p = 0; p < 4; ++p) {
      const int n = nw + p;
      jj[p] = (n < N) ? inds[(size_t)n * H + lane] : 0;
    }
    float cx[4], cy[4], cz[4];
    #pragma unroll
    for (int p = 0; p < 4; ++p) {
      int j = jj[p];
      if (j >= 0 && j < Ns) {
        cx[p] = s_pts[3 * j + 0];
        cy[p] = s_pts[3 * j + 1];
        cz[p] = s_pts[3 * j + 2];
      } else {
        cx[p] = cy[p] = cz[p] = 1e6f;   // shadow point -> zero influence
        jj[p] = 0;
      }
    }
    #pragma unroll
    for (int p = 0; p < 4; ++p) {
      const int n = nw + p;
      float qx = 0.f, qy = 0.f, qz = 0.f;
      if (n < N) {
        qx = q_pts[3 * n + 0];
        qy = q_pts[3 * n + 1];
        qz = q_pts[3 * n + 2];
      }
      sm.sP[wid][p][lane * 3 + 0] = cx[p] - qx;
      sm.sP[wid][p][lane * 3 + 1] = cy[p] - qy;
      sm.sP[wid][p][lane * 3 + 2] = cz[p] - qz;
      sm.sIdx[wid][p][lane] = jj[p];
    }
  } else if (lane < 28) {
    const int b = lane - H;
    #pragma unroll
    for (int p = 0; p < 4; ++p) {
      sm.sP[wid][p][78 + b * 3 + 0] = -1.0f;
      sm.sP[wid][p][78 + b * 3 + 1] = -1.0f;
      sm.sP[wid][p][78 + b * 3 + 2] = -1.0f;
    }
  }
  __syncwarp();

  // ── Phase 2 (batched): kp = gen_W @ p_vec + gen_b. ──
  if (lane < 30) {
    u64 aA[4] = {0, 0, 0, 0}, aB[4] = {0, 0, 0, 0};
    const u64* pp0 = reinterpret_cast<const u64*>(&sm.sP[wid][0][0]);
    const u64* pp1 = reinterpret_cast<const u64*>(&sm.sP[wid][1][0]);
    const u64* pp2 = reinterpret_cast<const u64*>(&sm.sP[wid][2][0]);
    const u64* pp3 = reinterpret_cast<const u64*>(&sm.sP[wid][3][0]);
    #pragma unroll 7
    for (int m2 = 0; m2 < 21; ++m2) {
      const u64 wA = sm.genWT2[m2 * 32 + lane];
      const u64 wB = sm.genWT2[(m2 + 21) * 32 + lane];
      aA[0] = ffma2(wA, pp0[m2], aA[0]);  aB[0] = ffma2(wB, pp0[m2 + 21], aB[0]);
      aA[1] = ffma2(wA, pp1[m2], aA[1]);  aB[1] = ffma2(wB, pp1[m2 + 21], aB[1]);
      aA[2] = ffma2(wA, pp2[m2], aA[2]);  aB[2] = ffma2(wB, pp2[m2 + 21], aB[2]);
      aA[3] = ffma2(wA, pp3[m2], aA[3]);  aB[3] = ffma2(wB, pp3[m2 + 21], aB[3]);
    }
    const float gb = sm.genB[lane];
    #pragma unroll
    for (int p = 0; p < 4; ++p) {
      const float2 ra = unpack2(aA[p]);
      const float2 rb = unpack2(aB[p]);
      sm.sKP[wid][p][lane] = (ra.x + ra.y) + (rb.x + rb.y) + gb;
    }
  }
  __syncwarp();

  const uint32_t xb = smem_u32(&sm.xT[wid][0]);
  const uint32_t wb = smem_u32(&sm.wT[wid][0]);

  // ── Phases 3-4 per point. ──
  for (int p = 0; p < 4; ++p) {
    const int n = nw + p;
    const int* idx = &sm.sIdx[wid][p][0];

    // Kick off x-row gather into xT (26 rows x 128 B = 208 16B chunks).
    #pragma unroll
    for (int i = 0; i < 7; ++i) {
      const int id = lane + i * 32;
      if (id < 208) {
        const int h = id >> 3;
        const int c = id & 7;
        const uint32_t dst = xb + h * 128 + ((c * 16) ^ ((h & 7) << 4));
        cp16(dst, g_X + (size_t)idx[h] * CIN + c * 8);
      }
    }
    cp_commit();

    __syncwarp();   // prior point's wT consumption finished

    // Phase 3 (overlaps cp.async): w[k][h] fp16 into wT.
    for (int t = lane; t < KP * H; t += 32) {
      const int k = t / H;
      const int h = t - k * H;
      const float dx = sm.sP[wid][p][h * 3 + 0] - sm.sKP[wid][p][k * 3 + 0];
      const float dy = sm.sP[wid][p][h * 3 + 1] - sm.sKP[wid][p][k * 3 + 1];
      const float dz = sm.sP[wid][p][h * 3 + 2] - sm.sKP[wid][p][k * 3 + 2];
      const float d  = sqrtf(fmaf(dx, dx, fmaf(dy, dy, dz * dz)));
      sm.wT[wid][k * 40 + h] =
          __float2half(fmaxf(1.0f - d * INV_EXT, 0.0f));
    }
    cp_wait0();
    __syncwarp();

    // A frags: wT 16x32, pitch 80 (conflict-free: 5 coprime 8).
    uint32_t a0[4], a1[4];
    const uint32_t aaddr = wb + (lane & 15) * 80 + ((lane >> 4) << 4);
    ldm4(a0, aaddr);
    ldm4(a1, aaddr + 32);

    // B frags (trans) + mma: weighted[16x64] = wT @ xT.
    float acc[8][4];
    #pragma unroll
    for (int j = 0; j < 8; ++j)
      #pragma unroll
      for (int q = 0; q < 4; ++q) acc[j][q] = 0.f;

    #pragma unroll
    for (int ks = 0; ks < 2; ++ks) {
      const uint32_t* ak = ks ? a1 : a0;
      #pragma unroll
      for (int nb = 0; nb < 4; ++nb) {
        const int kr = ks * 16 + (lane & 15);
        const uint32_t colB =
            (uint32_t)(nb * 32 + ((lane >> 4) << 4)) ^ ((kr & 7) << 4);
        uint32_t t4[4];
        ldm4t(t4, xb + kr * 128 + colB);
        mma16816(acc[2 * nb + 0], ak, t4);       // n8 tile: t4[0], t4[1]
        mma16816(acc[2 * nb + 1], ak, t4 + 2);   // n8 tile: t4[2], t4[3]
      }
    }

    // Store valid rows (k = g always; k = g+8 only for g < 2) as fp16.
    if (n < N) {
      const int g  = lane >> 2;
      const int tc = (lane & 3) * 2;
      __half* base = g_A + (size_t)n * KDIM;
      #pragma unroll
      for (int j = 0; j < 8; ++j) {
        const int col = j * 8 + tc;
        *reinterpret_cast<__half2*>(base + g * 64 + col) =
            __floats2half2_rn(acc[j][0], acc[j][1]);
        if (g < 2)
          *reinterpret_cast<__half2*>(base + (g + 8) * 64 + col) =
              __floats2half2_rn(acc[j][2], acc[j][3]);
      }
    }
  }
}

// ───────────────────── Kernel 2: fp16 mma.sync GEMM (round-8, unchanged) ────────

constexpr int KT      = 32;
constexpr int PITCH   = 80;
constexpr int TSZ     = 128 * PITCH;
constexpr int STAGE   = 2 * TSZ;
constexpr int NSTAGES = 4;
constexpr int GSMEM   = NSTAGES * STAGE;   // 81920 B
constexpr int NKT     = KDIM / KT;         // 20
constexpr int GNT     = 128;

__global__ void __launch_bounds__(GNT, 2)
gemm_kernel(float* __restrict__ out, int N)
{
  extern __shared__ char sm[];
  const uint32_t sb = smem_u32(sm);
  const int tid  = threadIdx.x;
  const int lane = tid & 31;
  const int wid  = tid >> 5;
  const int wr   = wid >> 1;
  const int wc   = wid & 1;
  const size_t n0 = (size_t)blockIdx.x * 128;

  auto load_stage = [&](int st, int kc) {
    const uint32_t base = sb + st * STAGE;
    #pragma unroll
    for (int i = 0; i < 4; ++i) {
      const int id = tid + i * GNT;
      const int r  = id >> 2;
      const int c  = id & 3;
      const uint32_t d = r * PITCH + c * 16;
      cp16(base + 0 * TSZ + d, g_A + (n0 + r) * KDIM + kc * KT + c * 8);
      cp16(base + 1 * TSZ + d, g_B + (size_t)r * KDIM + kc * KT + c * 8);
    }
  };

  load_stage(0, 0); cp_commit();
  load_stage(1, 1); cp_commit();
  load_stage(2, 2); cp_commit();

  const int arow  = lane & 15;
  const int acolB = (lane >> 4) * 16;
  const int brow  = (lane & 7) + ((lane >> 4) << 3);
  const int bcolB = ((lane >> 3) & 1) * 16;

  float acc[4][8][4];
  #pragma unroll
  for (int mi = 0; mi < 4; ++mi)
    #pragma unroll
    for (int ni = 0; ni < 8; ++ni)
      #pragma unroll
      for (int j = 0; j < 4; ++j) acc[mi][ni][j] = 0.f;

  for (int kc = 0; kc < NKT; ++kc) {
    const int st = kc & (NSTAGES - 1);
    cp_wait2();
    __syncthreads();

    if (kc + 3 < NKT) load_stage((kc + 3) & (NSTAGES - 1), kc + 3);
    cp_commit();

    const uint32_t tA = sb + st * STAGE + 0 * TSZ;
    const uint32_t tB = sb + st * STAGE + 1 * TSZ;

    #pragma unroll
    for (int ks = 0; ks < 2; ++ks) {
      uint32_t ah[4][4], bh[8][2];
      #pragma unroll
      for (int mi = 0; mi < 4; ++mi) {
        const uint32_t ao = (wr * 64 + mi * 16 + arow) * PITCH + ks * 32 + acolB;
        ldm4(ah[mi], tA + ao);
      }
      #pragma unroll
      for (int bi = 0; bi < 4; ++bi) {
        const uint32_t bo = (wc * 64 + bi * 16 + brow) * PITCH + ks * 32 + bcolB;
        uint32_t t4[4];
        ldm4(t4, tB + bo);
        bh[2 * bi][0] = t4[0]; bh[2 * bi][1] = t4[1];
        bh[2 * bi + 1][0] = t4[2]; bh[2 * bi + 1][1] = t4[3];
      }
      #pragma unroll
      for (int mi = 0; mi < 4; ++mi)
        #pragma unroll
        for (int ni = 0; ni < 8; ++ni)
          mma16816(acc[mi][ni], ah[mi], bh[ni]);
    }
  }

  const int trow = lane >> 2;
  const int tcol = (lane & 3) * 2;
  #pragma unroll
  for (int mi = 0; mi < 4; ++mi) {
    const size_t row = n0 + wr * 64 + mi * 16 + trow;
    #pragma unroll
    for (int ni = 0; ni < 8; ++ni) {
      const int col = wc * 64 + ni * 8 + tcol;
      if (row < (size_t)N) {
        *reinterpret_cast<float2*>(out + row * COUT + col) =
            make_float2(acc[mi][ni][0], acc[mi][ni][1]);
        *reinterpret_cast<float2*>(out + (row + 8) * COUT + col) =
            make_float2(acc[mi][ni][2], acc[mi][ni][3]);
      }
    }
  }
}

}  // namespace

// ───────────────────────────── launch ─────────────────────────────

extern "C" void kernel_launch(void* const* d_in, const int* in_sizes, int n_in,
                              void* d_out, int out_size) {
  const float* q_pts = (const float*)d_in[0];
  const float* s_pts = (const float*)d_in[1];
  const float* x     = (const float*)d_in[2];
  const float* genW  = (const float*)d_in[3];
  const float* genB  = (const float*)d_in[4];
  const float* wts   = (const float*)d_in[5];
  const int*   inds  = (const int*)d_in[6];
  float* out = (float*)d_out;

  int N  = in_sizes[0] / 3;
  const int Ns = in_sizes[1] / 3;
  if (N > MAXN) N = MAXN;

  cudaFuncSetAttribute(producer_kernel,
                       cudaFuncAttributeMaxDynamicSharedMemorySize, PSMEM);
  cudaFuncSetAttribute(gemm_kernel,
                       cudaFuncAttributeMaxDynamicSharedMemorySize, GSMEM);

  prep_kernel<<<1024, 256>>>(x, wts, N * CIN);

  const int grid1 = (N + TILE - 1) / TILE;
  producer_kernel<<<grid1, NT, PSMEM>>>(q_pts, s_pts, genW, genB, inds, N, Ns);

  const int grid3 = (N + 127) / 128;
  gemm_kernel<<<grid3, GNT, GSMEM>>>(out, N);
}